// round 17
// baseline (speedup 1.0000x reference)
#include <cuda_runtime.h>
#include <math.h>

// RoPE-2D: x[B=32, S=1024, H=16, D=64] fp32, grid_sizes[B,2] int32.
// Combined rotation: rot(i*th) ∘ rot(j*th) == rot((i+j)*th)  -> one
// {cos,sin} pair per rotation pair instead of two gathers + 8 FMAs.
//
// FINAL (best measured across 15 rounds): one-shot grid, block=64 covering
// ONE s-row, 4 float4/thread front-batched with __ldcs; __stcs evict-first
// stores (measured better than .wb). All 4 vectors of a thread share one
// pos -> 2 sincos/thread, fully hidden under DRAM latency (issue ~17%).
//
// Measured verdicts: MLP 4 optimal (8 loses via regs at block 256 AND 64);
// block 64/128 tied > 256; persistent grid loses; smem tables lose;
// .cs loads+stores win; 256-bit ld/st neutral. Kernel streams at ~94% of
// the 8 TB/s HBM spec on its mandatory 268 MB — the floor for this op.

#define F4_PER_ROW 16        // D=64 floats = 16 float4
#define S_LOG2 10

__global__ void __launch_bounds__(64) rope2d_kernel(const float4* __restrict__ x,
                                                    const int* __restrict__ grid_sizes,
                                                    float4* __restrict__ out) {
    int tid = threadIdx.x;                 // 0..63
    int f0 = blockIdx.x * 256 + tid;
    // Block covers one s-row = 256 float4. Thread handles
    // f0, f0+64, f0+128, f0+192 (same (b,s), same t, different heads).

    // ---- front-batch the 4 streaming loads (MLP_p1 = 4) ----
    float4 v0 = __ldcs(&x[f0]);
    float4 v1 = __ldcs(&x[f0 + 64]);
    float4 v2 = __ldcs(&x[f0 + 128]);
    float4 v3 = __ldcs(&x[f0 + 192]);

    // ---- position for this row ----
    unsigned row = blockIdx.x;
    unsigned s = row & ((1u << S_LOG2) - 1u);
    unsigned b = row >> S_LOG2;
    unsigned cols = (unsigned)__ldg(&grid_sizes[2 * b + 1]);
    unsigned i = s / cols;
    unsigned j = s - i * cols;
    int pos = (int)(i + j);

    // theta_k = 10000^(-k/32) = exp2(-k * log2(10000)/32)
    int t = tid & (F4_PER_ROW - 1);        // pairs k=2t, 2t+1
    const float C = 13.287712379549449f / 32.0f;   // log2(10000)/32
    const float R = 0.7498942093324559f;           // 10000^(-1/32)
    float th0 = exp2f(-(float)(2 * t) * C);
    float th1 = th0 * R;

    float ca, sa, cb, sb;
    __sincosf((float)pos * th0, &sa, &ca);
    __sincosf((float)pos * th1, &sb, &cb);

    float4 o0, o1, o2, o3;
    o0.x = fmaf(v0.x, ca, -v0.y * sa);
    o0.y = fmaf(v0.y, ca,  v0.x * sa);
    o0.z = fmaf(v0.z, cb, -v0.w * sb);
    o0.w = fmaf(v0.w, cb,  v0.z * sb);

    o1.x = fmaf(v1.x, ca, -v1.y * sa);
    o1.y = fmaf(v1.y, ca,  v1.x * sa);
    o1.z = fmaf(v1.z, cb, -v1.w * sb);
    o1.w = fmaf(v1.w, cb,  v1.z * sb);

    o2.x = fmaf(v2.x, ca, -v2.y * sa);
    o2.y = fmaf(v2.y, ca,  v2.x * sa);
    o2.z = fmaf(v2.z, cb, -v2.w * sb);
    o2.w = fmaf(v2.w, cb,  v2.z * sb);

    o3.x = fmaf(v3.x, ca, -v3.y * sa);
    o3.y = fmaf(v3.y, ca,  v3.x * sa);
    o3.z = fmaf(v3.z, cb, -v3.w * sb);
    o3.w = fmaf(v3.w, cb,  v3.z * sb);

    __stcs(&out[f0],       o0);
    __stcs(&out[f0 + 64],  o1);
    __stcs(&out[f0 + 128], o2);
    __stcs(&out[f0 + 192], o3);
}

extern "C" void kernel_launch(void* const* d_in, const int* in_sizes, int n_in,
                              void* d_out, int out_size) {
    const float4* x = (const float4*)d_in[0];
    const int* grid_sizes = (const int*)d_in[1];
    float4* out = (float4*)d_out;

    int total4 = in_sizes[0] / 4;            // 8,388,608 float4
    int nblocks = total4 / 256;              // 32768 blocks of 64 threads
    rope2d_kernel<<<nblocks, 64>>>(x, grid_sizes, out);
}